// round 3
// baseline (speedup 1.0000x reference)
#include <cuda_runtime.h>
#include <math.h>

// Problem constants
#define Bx 4
#define Lx 4096
#define Hx 8
#define Ex 64
#define Mx 64
#define Cx 512            // H*E
#define KP 2304           // padded folded K (>= 2049), = 9*256
#define NSPLIT 9
#define KCHUNK 256

typedef unsigned long long u64;

// Static device scratch (no allocations allowed)
__device__ float g_bc[Mx * KP];                 // cos(2*pi*m*l/L), [m][l], pads 0
__device__ float g_bs[Mx * KP];                 // -sin(...),       [m][l], pads 0
__device__ float g_bcT[KP * Mx];                // transposed [l][m]
__device__ float g_bsT[KP * Mx];
__device__ float g_part[8 * NSPLIT * Mx * Cx];  // split-K partials
__device__ float g_X[8 * Mx * Cx];              // X[bp][m][c], bp = b*2 + (0:Re,1:Im)
__device__ float g_res[Bx * Cx * 2 * Mx];       // res[b][c][0..63 ReS, 64..127 ImS]

// packed f32x2 helpers
__device__ __forceinline__ void fma2(u64& d, u64 a, u64 b) {
    asm("fma.rn.f32x2 %0, %1, %2, %0;" : "+l"(d) : "l"(a), "l"(b));
}
__device__ __forceinline__ float2 unpk(u64 v) {
    float2 r;
    asm("mov.b64 {%0, %1}, %2;" : "=f"(r.x), "=f"(r.y) : "l"(v));
    return r;
}
__device__ __forceinline__ u64 dup(float v) {
    u64 r;
    asm("mov.b64 %0, {%1, %1};" : "=l"(r) : "f"(v));
    return r;
}

// ---------------------------------------------------------------------------
// K0a: build basis tables [m][l].
// ---------------------------------------------------------------------------
__global__ void k_basis() {
    int id = blockIdx.x * blockDim.x + threadIdx.x;
    if (id >= Mx * KP) return;
    int m = id / KP, l = id - m * KP;
    float c = 0.f, s = 0.f;
    if (l <= 2048) {
        int r = (m * l) & (Lx - 1);
        sincospif((float)r / 2048.0f, &s, &c);
    }
    g_bc[m * KP + l] = c;
    g_bs[m * KP + l] = -s;
}

// ---------------------------------------------------------------------------
// K0b: transpose basis -> [l][m]
// ---------------------------------------------------------------------------
__global__ void k_basisT() {
    int id = blockIdx.x * blockDim.x + threadIdx.x;
    if (id >= Mx * KP) return;
    int l = id / Mx, m = id - l * Mx;
    g_bcT[(size_t)l * Mx + m] = g_bc[(size_t)m * KP + l];
    g_bsT[(size_t)l * Mx + m] = g_bs[(size_t)m * KP + l];
}

// ---------------------------------------------------------------------------
// K0c: zero g_X (harmless setup; keeps k_fwd at launch position 4 for ncu)
// ---------------------------------------------------------------------------
__global__ void k_zeroX() {
    int o = blockIdx.x * blockDim.x + threadIdx.x;
    ((float4*)g_X)[o] = make_float4(0.f, 0.f, 0.f, 0.f);
}

// ---------------------------------------------------------------------------
// K1: forward GEMM, split-K, fold fused, Re+Im fused, packed FFMA2.
//   Re[m][c] = sum_l bc[m][l] * (q[l]+q[L-l])[c]
//   Im[m][c] = sum_l bs[m][l] * (q[l]-q[L-l])[c]
// Block: 64 m x 128 c, 512 threads (4m x 4c per thread), K chunk = 256.
// ---------------------------------------------------------------------------
__global__ void __launch_bounds__(512) k_fwd(const float* __restrict__ q) {
    __shared__ float2 Ac[8][64];    // (bc,bc) duplicated pairs [kk][m]
    __shared__ float2 As[8][64];    // (bs,bs)
    __shared__ float2 Bsum[8][64];  // qs natural pairs [kk][c/2]
    __shared__ float2 Bdif[8][64];  // qd natural pairs

    int t = threadIdx.x;
    int ct = blockIdx.x;      // 0..3  (c-tile of 128)
    int split = blockIdx.y;   // 0..8
    int b = blockIdx.z;       // 0..3
    int c0 = ct * 128;
    int k0 = split * KCHUNK;
    int tx = t & 31, ty = t >> 5;   // tx: c-group (4c), ty: m-group (4m)

    u64 accRe[4][2], accIm[4][2];
#pragma unroll
    for (int r = 0; r < 4; r++) {
        accRe[r][0] = accRe[r][1] = 0ull;
        accIm[r][0] = accIm[r][1] = 0ull;
    }
    const float* qb = q + (size_t)b * Lx * Cx;

    for (int kc = k0; kc < k0 + KCHUNK; kc += 8) {
        if (t < 256) {
            int kk = t >> 5, cg = t & 31;   // 8 kk x 32 float4-cols = 128 c
            int l = kc + kk;
            float4 a = make_float4(0.f, 0.f, 0.f, 0.f);
            float4 mm = make_float4(0.f, 0.f, 0.f, 0.f);
            bool half = (l == 0) || (l == 2048);
            if (l <= 2048) {
                a = *(const float4*)(qb + (size_t)l * Cx + c0 + cg * 4);
                if (!half)
                    mm = *(const float4*)(qb + (size_t)(Lx - l) * Cx + c0 + cg * 4);
            }
            float4 vs, vd;
            if (half) {
                vs = a; vd = make_float4(0.f, 0.f, 0.f, 0.f);
            } else {
                vs = make_float4(a.x + mm.x, a.y + mm.y, a.z + mm.z, a.w + mm.w);
                vd = make_float4(a.x - mm.x, a.y - mm.y, a.z - mm.z, a.w - mm.w);
            }
            Bsum[kk][cg * 2]     = make_float2(vs.x, vs.y);
            Bsum[kk][cg * 2 + 1] = make_float2(vs.z, vs.w);
            Bdif[kk][cg * 2]     = make_float2(vd.x, vd.y);
            Bdif[kk][cg * 2 + 1] = make_float2(vd.z, vd.w);
        } else if (t < 384) {
            int t2 = t - 256;
            int kk = t2 >> 4, mg = t2 & 15;  // 8 kk x 16 float4-groups = 64 m
            int l = kc + kk;
            float4 c4 = *(const float4*)(g_bcT + (size_t)l * Mx + mg * 4);
            float4 s4 = *(const float4*)(g_bsT + (size_t)l * Mx + mg * 4);
            Ac[kk][mg * 4 + 0] = make_float2(c4.x, c4.x);
            Ac[kk][mg * 4 + 1] = make_float2(c4.y, c4.y);
            Ac[kk][mg * 4 + 2] = make_float2(c4.z, c4.z);
            Ac[kk][mg * 4 + 3] = make_float2(c4.w, c4.w);
            As[kk][mg * 4 + 0] = make_float2(s4.x, s4.x);
            As[kk][mg * 4 + 1] = make_float2(s4.y, s4.y);
            As[kk][mg * 4 + 2] = make_float2(s4.z, s4.z);
            As[kk][mg * 4 + 3] = make_float2(s4.w, s4.w);
        }
        __syncthreads();
#pragma unroll
        for (int kk = 0; kk < 8; kk++) {
            u64 b0 = *(const u64*)&Bsum[kk][tx * 2];
            u64 b1 = *(const u64*)&Bsum[kk][tx * 2 + 1];
            u64 d0 = *(const u64*)&Bdif[kk][tx * 2];
            u64 d1 = *(const u64*)&Bdif[kk][tx * 2 + 1];
#pragma unroll
            for (int r = 0; r < 4; r++) {
                u64 ac = *(const u64*)&Ac[kk][ty * 4 + r];
                u64 as = *(const u64*)&As[kk][ty * 4 + r];
                fma2(accRe[r][0], ac, b0);
                fma2(accRe[r][1], ac, b1);
                fma2(accIm[r][0], as, d0);
                fma2(accIm[r][1], as, d1);
            }
        }
        __syncthreads();
    }

    float* oRe = g_part + ((size_t)(b * 2 + 0) * NSPLIT + split) * (Mx * Cx);
    float* oIm = g_part + ((size_t)(b * 2 + 1) * NSPLIT + split) * (Mx * Cx);
#pragma unroll
    for (int r = 0; r < 4; r++) {
        int m = ty * 4 + r;
        float2 lo = unpk(accRe[r][0]), hi = unpk(accRe[r][1]);
        *(float4*)(oRe + (size_t)m * Cx + c0 + tx * 4) =
            make_float4(lo.x, lo.y, hi.x, hi.y);
        float2 lo2 = unpk(accIm[r][0]), hi2 = unpk(accIm[r][1]);
        *(float4*)(oIm + (size_t)m * Cx + c0 + tx * 4) =
            make_float4(lo2.x, lo2.y, hi2.x, hi2.y);
    }
}

// ---------------------------------------------------------------------------
// K2: reduce split-K partials -> g_X (float4)
// ---------------------------------------------------------------------------
__global__ void k_reduce() {
    int o4 = blockIdx.x * blockDim.x + threadIdx.x;  // 0..65535 (float4 units)
    int bp = o4 >> 13;           // 8192 float4 per bp
    int inner = o4 & 8191;
    const float4* p = (const float4*)g_part + (size_t)bp * NSPLIT * 8192 + inner;
    float4 s = make_float4(0.f, 0.f, 0.f, 0.f);
#pragma unroll
    for (int sp = 0; sp < NSPLIT; sp++) {
        float4 v = p[(size_t)sp * 8192];
        s.x += v.x; s.y += v.y; s.z += v.z; s.w += v.w;
    }
    ((float4*)g_X)[o4] = s;
}

// ---------------------------------------------------------------------------
// K3: head mixing + irfft scaling. Block = (e-quad, o, b); 256 threads (m,eq).
// X tile staged in smem with m-contiguous layout (conflict-free reads).
// ---------------------------------------------------------------------------
__global__ void k_mix(const float* __restrict__ wr, const float* __restrict__ wi) {
    __shared__ float sX[2][8][4][64];   // [re/im][i][eq][m]
    int t = threadIdx.x;
    int eq4 = blockIdx.x;   // 0..15 -> e0 = eq4*4
    int o = blockIdx.y;     // 0..7
    int b = blockIdx.z;     // 0..3
    int e0 = eq4 * 4;

    // load 2 * 64m * 8i float4 (along e) = 1024 float4
#pragma unroll
    for (int s = 0; s < 4; s++) {
        int idx = t + 256 * s;
        int tab = idx >> 9;
        int rem = idx & 511;
        int m = rem >> 3, i = rem & 7;
        float4 v = *(const float4*)(g_X + ((size_t)(b * 2 + tab) * Mx + m) * Cx + i * 64 + e0);
        sX[tab][i][0][m] = v.x;
        sX[tab][i][1][m] = v.y;
        sX[tab][i][2][m] = v.z;
        sX[tab][i][3][m] = v.w;
    }
    __syncthreads();

    int m = t & 63, eqi = t >> 6;
    int e = e0 + eqi;
    float re = 0.f, im = 0.f;
#pragma unroll
    for (int i = 0; i < Hx; i++) {
        float xr = sX[0][i][eqi][m];
        float xi = sX[1][i][eqi][m];
        size_t wIdx = (((size_t)i * Hx + o) * Ex + e) * Mx + m;
        float wre = wr[wIdx], wim = wi[wIdx];
        re += xr * wre - xi * wim;
        im += xr * wim + xi * wre;
    }
    float scR = (m == 0) ? (1.0f / Lx) : (2.0f / Lx);
    float* r = g_res + ((size_t)(b * Cx) + o * Ex + e) * 128;
    r[m] = re * scR;
    r[64 + m] = (m == 0) ? 0.f : im * (2.0f / Lx);
}

// ---------------------------------------------------------------------------
// K4: inverse synthesis with mirror writes, packed FFMA2.
//   E[l] = sum_m ReS*bc[m][l];  O[l] = sum_m ImS*bs[m][l]
//   out[l] = E+O (l=0..2047); out[L-l] = E-O (l=1..2047)
// Block: 64 rows x 128 l, 256 threads, 4 rows x 8 l per thread.
// ---------------------------------------------------------------------------
__global__ void __launch_bounds__(256) k_inv(float* __restrict__ out) {
    __shared__ float sa[64][128];        // [row][m | 64+m]
    __shared__ float4 sbc[16][32];       // [m-chunk][l/4]
    __shared__ float4 sbs[16][32];
    int t = threadIdx.x;
    int ltile = blockIdx.x;              // 0..15
    int rowBase = blockIdx.y * 64;       // 32 blocks
    int l0b = ltile * 128;

    // load res tile: 64 rows x 128 = 2048 float4
#pragma unroll
    for (int s = 0; s < 8; s++) {
        int i4 = t + 256 * s;
        int r = i4 >> 5, j = i4 & 31;
        ((float4*)sa[r])[j] = *(const float4*)(g_res + (size_t)(rowBase + r) * 128 + j * 4);
    }

    int tx = t & 15, ty = t >> 4;        // tx: l-group (8 l), ty: row-group (4 rows)
    int l0 = l0b + tx * 8;
    u64 E[4][4], O[4][4];
#pragma unroll
    for (int r = 0; r < 4; r++)
#pragma unroll
        for (int j = 0; j < 4; j++) { E[r][j] = 0ull; O[r][j] = 0ull; }

    for (int ch = 0; ch < 4; ch++) {
        __syncthreads();                 // also covers initial sa stores
#pragma unroll
        for (int s = 0; s < 2; s++) {
            int i4 = t + 256 * s;        // 512 float4 per table
            int mr = i4 >> 5, j = i4 & 31;
            sbc[mr][j] = *(const float4*)(g_bc + (size_t)(ch * 16 + mr) * KP + l0b + j * 4);
            sbs[mr][j] = *(const float4*)(g_bs + (size_t)(ch * 16 + mr) * KP + l0b + j * 4);
        }
        __syncthreads();
#pragma unroll
        for (int mm = 0; mm < 16; mm++) {
            int m = ch * 16 + mm;
            float4 c0 = sbc[mm][tx * 2];
            float4 c1 = sbc[mm][tx * 2 + 1];
            float4 s0 = sbs[mm][tx * 2];
            float4 s1 = sbs[mm][tx * 2 + 1];
            u64 cp0 = *(u64*)&c0.x, cp1 = *(u64*)&c0.z;
            u64 cp2 = *(u64*)&c1.x, cp3 = *(u64*)&c1.z;
            u64 sp0 = *(u64*)&s0.x, sp1 = *(u64*)&s0.z;
            u64 sp2 = *(u64*)&s1.x, sp3 = *(u64*)&s1.z;
#pragma unroll
            for (int r = 0; r < 4; r++) {
                u64 ar = dup(sa[ty * 4 + r][m]);
                u64 ai = dup(sa[ty * 4 + r][64 + m]);
                fma2(E[r][0], ar, cp0);
                fma2(E[r][1], ar, cp1);
                fma2(E[r][2], ar, cp2);
                fma2(E[r][3], ar, cp3);
                fma2(O[r][0], ai, sp0);
                fma2(O[r][1], ai, sp1);
                fma2(O[r][2], ai, sp2);
                fma2(O[r][3], ai, sp3);
            }
        }
    }

#pragma unroll
    for (int r = 0; r < 4; r++) {
        int row = rowBase + ty * 4 + r;
        float ev[8], ov[8];
#pragma unroll
        for (int j = 0; j < 4; j++) {
            float2 e2 = unpk(E[r][j]);
            float2 o2 = unpk(O[r][j]);
            ev[j * 2] = e2.x; ev[j * 2 + 1] = e2.y;
            ov[j * 2] = o2.x; ov[j * 2 + 1] = o2.y;
        }
        float4 v0 = make_float4(ev[0] + ov[0], ev[1] + ov[1], ev[2] + ov[2], ev[3] + ov[3]);
        float4 v1 = make_float4(ev[4] + ov[4], ev[5] + ov[5], ev[6] + ov[6], ev[7] + ov[7]);
        *(float4*)(out + (size_t)row * Lx + l0) = v0;
        *(float4*)(out + (size_t)row * Lx + l0 + 4) = v1;
        // mirror stores (scalar; misaligned when reversed)
#pragma unroll
        for (int u = 0; u < 8; u++) {
            int l = l0 + u;
            if (l > 0) out[(size_t)row * Lx + (Lx - l)] = ev[u] - ov[u];
        }
    }
}

// ---------------------------------------------------------------------------
// K5: l = 2048 edge. bc[m][2048] = (-1)^m, bs = 0.
// ---------------------------------------------------------------------------
__global__ void k_edge(float* __restrict__ out) {
    int row = blockIdx.x * blockDim.x + threadIdx.x;  // 0..2047
    const float* r = g_res + (size_t)row * 128;
    float s = 0.f;
#pragma unroll
    for (int m = 0; m < 64; m += 2) { s += r[m]; s -= r[m + 1]; }
    out[(size_t)row * Lx + 2048] = s;
}

// ---------------------------------------------------------------------------
extern "C" void kernel_launch(void* const* d_in, const int* in_sizes, int n_in,
                              void* d_out, int out_size) {
    const float* q  = (const float*)d_in[0];
    // d_in[1]=k, d_in[2]=v unused by reference
    const float* wr = (const float*)d_in[3];
    const float* wi = (const float*)d_in[4];
    float* out = (float*)d_out;

    k_basis<<<(Mx * KP + 255) / 256, 256>>>();
    k_basisT<<<(Mx * KP + 255) / 256, 256>>>();
    k_zeroX<<<(8 * Mx * Cx / 4) / 256, 256>>>();
    {
        dim3 g(4, NSPLIT, Bx);   // 4 c-tiles x 9 splits x 4 batches = 144 blocks
        k_fwd<<<g, 512>>>(q);    // <- 4th launch: profiled by ncu
    }
    k_reduce<<<256, 256>>>();
    {
        dim3 g(16, 8, 4);
        k_mix<<<g, 256>>>(wr, wi);
    }
    {
        dim3 g(16, 32);
        k_inv<<<g, 256>>>(out);
    }
    k_edge<<<8, 256>>>(out);
}

// round 4
// speedup vs baseline: 1.3499x; 1.3499x over previous
#include <cuda_runtime.h>
#include <math.h>

// Problem constants
#define Bx 4
#define Lx 4096
#define Hx 8
#define Ex 64
#define Mx 64
#define Cx 512            // H*E
#define KP 2304           // padded folded K (>= 2049), = 18*128
#define NSPLIT 18
#define KCHUNK 128

typedef unsigned long long u64;

// Static device scratch (no allocations allowed)
__device__ float g_bc[Mx * KP];                 // cos(2*pi*m*l/L), [m][l], pads 0
__device__ float g_bs[Mx * KP];                 // -sin(...),       [m][l], pads 0
__device__ float g_bcT[KP * Mx];                // transposed [l][m]
__device__ float g_bsT[KP * Mx];
__device__ float g_part[8 * NSPLIT * Mx * Cx];  // split-K partials
__device__ float g_X[8 * Mx * Cx];              // X[bp][m][c], bp = b*2 + (0:Re,1:Im)
__device__ float g_res[Bx * Cx * 2 * Mx];       // res[b][c][0..63 ReS | 64..127 ImS]

// packed f32x2 helpers
__device__ __forceinline__ void fma2(u64& d, u64 a, u64 b) {
    asm("fma.rn.f32x2 %0, %1, %2, %0;" : "+l"(d) : "l"(a), "l"(b));
}
__device__ __forceinline__ float2 unpk(u64 v) {
    float2 r;
    asm("mov.b64 {%0, %1}, %2;" : "=f"(r.x), "=f"(r.y) : "l"(v));
    return r;
}
__device__ __forceinline__ u64 dup(float v) {
    u64 r;
    asm("mov.b64 %0, {%1, %1};" : "=l"(r) : "f"(v));
    return r;
}

// ---------------------------------------------------------------------------
// K0a: build basis tables [m][l].
// ---------------------------------------------------------------------------
__global__ void k_basis() {
    int id = blockIdx.x * blockDim.x + threadIdx.x;
    if (id >= Mx * KP) return;
    int m = id / KP, l = id - m * KP;
    float c = 0.f, s = 0.f;
    if (l <= 2048) {
        int r = (m * l) & (Lx - 1);
        sincospif((float)r / 2048.0f, &s, &c);
    }
    g_bc[m * KP + l] = c;
    g_bs[m * KP + l] = -s;
}

// ---------------------------------------------------------------------------
// K0b: transpose basis -> [l][m]
// ---------------------------------------------------------------------------
__global__ void k_basisT() {
    int id = blockIdx.x * blockDim.x + threadIdx.x;
    if (id >= Mx * KP) return;
    int l = id / Mx, m = id - l * Mx;
    g_bcT[(size_t)l * Mx + m] = g_bc[(size_t)m * KP + l];
    g_bsT[(size_t)l * Mx + m] = g_bs[(size_t)m * KP + l];
}

// ---------------------------------------------------------------------------
// K0c: zero g_X (keeps k_fwd at launch position 4 for ncu)
// ---------------------------------------------------------------------------
__global__ void k_zeroX() {
    int o = blockIdx.x * blockDim.x + threadIdx.x;
    ((float4*)g_X)[o] = make_float4(0.f, 0.f, 0.f, 0.f);
}

// ---------------------------------------------------------------------------
// K1: forward GEMM, split-K, fold fused, Re+Im fused, packed FFMA2.
//   Re[m][c] = sum_l bc[m][l] * (q[l]+q[L-l])[c]
//   Im[m][c] = sum_l bs[m][l] * (q[l]-q[L-l])[c]
// Block: 64 m x 256 c, 512 threads, per thread 8m x 4c. A non-dup in smem,
// duplicated into register pairs on ALU pipe.
// ---------------------------------------------------------------------------
__global__ void __launch_bounds__(512) k_fwd(const float* __restrict__ q) {
    __shared__ float2 Bsum[8][128];  // [kk][c/2], natural pairs
    __shared__ float2 Bdif[8][128];
    __shared__ float Acs[8][64];     // [kk][m] non-duplicated
    __shared__ float Ass[8][64];

    int t = threadIdx.x;
    int ct = blockIdx.x;      // 0..1  (c-tile of 256)
    int split = blockIdx.y;   // 0..17
    int b = blockIdx.z;       // 0..3
    int c0 = ct * 256;
    int k0 = split * KCHUNK;
    int tx = t & 63, ty = t >> 6;   // tx: c-group (4c), ty: m-group (8m), uniform/warp

    u64 accRe[8][2], accIm[8][2];
#pragma unroll
    for (int r = 0; r < 8; r++) {
        accRe[r][0] = accRe[r][1] = 0ull;
        accIm[r][0] = accIm[r][1] = 0ull;
    }
    const float* qb = q + (size_t)b * Lx * Cx;

    for (int kc = k0; kc < k0 + KCHUNK; kc += 8) {
        // B loaders: all 512 threads. kk = t>>6, cg = t&63 (64 float4 = 256 c)
        {
            int kk = t >> 6, cg = t & 63;
            int l = kc + kk;
            float4 a = make_float4(0.f, 0.f, 0.f, 0.f);
            float4 mm = make_float4(0.f, 0.f, 0.f, 0.f);
            bool half = (l == 0) || (l == 2048);
            if (l <= 2048) {
                a = *(const float4*)(qb + (size_t)l * Cx + c0 + cg * 4);
                if (!half)
                    mm = *(const float4*)(qb + (size_t)(Lx - l) * Cx + c0 + cg * 4);
            }
            float4 vs, vd;
            if (half) {
                vs = a; vd = make_float4(0.f, 0.f, 0.f, 0.f);
            } else {
                vs = make_float4(a.x + mm.x, a.y + mm.y, a.z + mm.z, a.w + mm.w);
                vd = make_float4(a.x - mm.x, a.y - mm.y, a.z - mm.z, a.w - mm.w);
            }
            *(float4*)&Bsum[kk][cg * 2] = vs;
            *(float4*)&Bdif[kk][cg * 2] = vd;
        }
        // A loaders: t < 128: kk = t>>4, mg = t&15 (16 float4 = 64 m)
        if (t < 128) {
            int kk = t >> 4, mg = t & 15;
            int l = kc + kk;
            *(float4*)&Acs[kk][mg * 4] = *(const float4*)(g_bcT + (size_t)l * Mx + mg * 4);
            *(float4*)&Ass[kk][mg * 4] = *(const float4*)(g_bsT + (size_t)l * Mx + mg * 4);
        }
        __syncthreads();
#pragma unroll
        for (int kk = 0; kk < 8; kk++) {
            u64 b0 = *(const u64*)&Bsum[kk][tx * 2];
            u64 b1 = *(const u64*)&Bsum[kk][tx * 2 + 1];
            u64 d0 = *(const u64*)&Bdif[kk][tx * 2];
            u64 d1 = *(const u64*)&Bdif[kk][tx * 2 + 1];
            float4 ac0 = *(const float4*)&Acs[kk][ty * 8];       // uniform
            float4 ac1 = *(const float4*)&Acs[kk][ty * 8 + 4];
            float4 as0 = *(const float4*)&Ass[kk][ty * 8];
            float4 as1 = *(const float4*)&Ass[kk][ty * 8 + 4];
            float acv[8] = {ac0.x, ac0.y, ac0.z, ac0.w, ac1.x, ac1.y, ac1.z, ac1.w};
            float asv[8] = {as0.x, as0.y, as0.z, as0.w, as1.x, as1.y, as1.z, as1.w};
#pragma unroll
            for (int r = 0; r < 8; r++) {
                u64 a2 = dup(acv[r]);
                u64 s2 = dup(asv[r]);
                fma2(accRe[r][0], a2, b0);
                fma2(accRe[r][1], a2, b1);
                fma2(accIm[r][0], s2, d0);
                fma2(accIm[r][1], s2, d1);
            }
        }
        __syncthreads();
    }

    float* oRe = g_part + ((size_t)(b * 2 + 0) * NSPLIT + split) * (Mx * Cx);
    float* oIm = g_part + ((size_t)(b * 2 + 1) * NSPLIT + split) * (Mx * Cx);
#pragma unroll
    for (int r = 0; r < 8; r++) {
        int m = ty * 8 + r;
        float2 lo = unpk(accRe[r][0]), hi = unpk(accRe[r][1]);
        *(float4*)(oRe + (size_t)m * Cx + c0 + tx * 4) =
            make_float4(lo.x, lo.y, hi.x, hi.y);
        float2 lo2 = unpk(accIm[r][0]), hi2 = unpk(accIm[r][1]);
        *(float4*)(oIm + (size_t)m * Cx + c0 + tx * 4) =
            make_float4(lo2.x, lo2.y, hi2.x, hi2.y);
    }
}

// ---------------------------------------------------------------------------
// K2: reduce split-K partials -> g_X (float4)
// ---------------------------------------------------------------------------
__global__ void k_reduce() {
    int o4 = blockIdx.x * blockDim.x + threadIdx.x;  // 0..65535 (float4 units)
    int bp = o4 >> 13;           // 8192 float4 per bp
    int inner = o4 & 8191;
    const float4* p = (const float4*)g_part + (size_t)bp * NSPLIT * 8192 + inner;
    float4 s = make_float4(0.f, 0.f, 0.f, 0.f);
#pragma unroll
    for (int sp = 0; sp < NSPLIT; sp++) {
        float4 v = p[(size_t)sp * 8192];
        s.x += v.x; s.y += v.y; s.z += v.z; s.w += v.w;
    }
    ((float4*)g_X)[o4] = s;
}

// ---------------------------------------------------------------------------
// K3: head mixing + irfft scaling. Block = (e-quad, o, b); 256 threads (m,eq).
// ---------------------------------------------------------------------------
__global__ void k_mix(const float* __restrict__ wr, const float* __restrict__ wi) {
    __shared__ float sX[2][8][4][64];   // [re/im][i][eq][m]
    int t = threadIdx.x;
    int eq4 = blockIdx.x;   // 0..15 -> e0 = eq4*4
    int o = blockIdx.y;     // 0..7
    int b = blockIdx.z;     // 0..3
    int e0 = eq4 * 4;

#pragma unroll
    for (int s = 0; s < 4; s++) {
        int idx = t + 256 * s;
        int tab = idx >> 9;
        int rem = idx & 511;
        int m = rem >> 3, i = rem & 7;
        float4 v = *(const float4*)(g_X + ((size_t)(b * 2 + tab) * Mx + m) * Cx + i * 64 + e0);
        sX[tab][i][0][m] = v.x;
        sX[tab][i][1][m] = v.y;
        sX[tab][i][2][m] = v.z;
        sX[tab][i][3][m] = v.w;
    }
    __syncthreads();

    int m = t & 63, eqi = t >> 6;
    int e = e0 + eqi;
    float re = 0.f, im = 0.f;
#pragma unroll
    for (int i = 0; i < Hx; i++) {
        float xr = sX[0][i][eqi][m];
        float xi = sX[1][i][eqi][m];
        size_t wIdx = (((size_t)i * Hx + o) * Ex + e) * Mx + m;
        float wre = wr[wIdx], wim = wi[wIdx];
        re += xr * wre - xi * wim;
        im += xr * wim + xi * wre;
    }
    float scR = (m == 0) ? (1.0f / Lx) : (2.0f / Lx);
    float* r = g_res + ((size_t)(b * Cx) + o * Ex + e) * 128;
    r[m] = re * scR;
    r[64 + m] = (m == 0) ? 0.f : im * (2.0f / Lx);
}

// ---------------------------------------------------------------------------
// K4: inverse synthesis, row-pairs packed in f32x2 lanes.
//   E[l] = sum_m ReS*bc[m][l];  O[l] = sum_m ImS*bs[m][l]
//   out[l] = E+O (l<2048); out[L-l] = E-O (l=1..2047)
// Block: 64 rows x 256 l, 512 threads, per thread 8 rows x 4 l.
// Dynamic smem: saT[128][68] (transposed res) + sbc/sbs[16][256].
// ---------------------------------------------------------------------------
#define SAT_PAD 68
#define SMEM_INV (128 * SAT_PAD * 4 + 2 * 16 * 256 * 4)

__global__ void __launch_bounds__(512) k_inv(float* __restrict__ out) {
    extern __shared__ float sm[];
    float* saT = sm;                         // [j=0..127][row 0..63], stride 68
    float* sbc = sm + 128 * SAT_PAD;         // [16][256]
    float* sbs = sbc + 16 * 256;

    int t = threadIdx.x;
    int ltile = blockIdx.x;              // 0..7 (256 l each)
    int rowBase = blockIdx.y * 64;       // 0..31
    int l0b = ltile * 256;

    // load g_res into transposed saT: i4 = t + 512*s, row = i4&63, j4 = i4>>6
    // (within a warp j4 is fixed, row varies -> conflict-free column stores)
#pragma unroll
    for (int s = 0; s < 4; s++) {
        int i4 = t + 512 * s;
        int row = i4 & 63, j4 = i4 >> 6;     // j4 0..31
        float4 v = *(const float4*)(g_res + (size_t)(rowBase + row) * 128 + j4 * 4);
        saT[(j4 * 4 + 0) * SAT_PAD + row] = v.x;
        saT[(j4 * 4 + 1) * SAT_PAD + row] = v.y;
        saT[(j4 * 4 + 2) * SAT_PAD + row] = v.z;
        saT[(j4 * 4 + 3) * SAT_PAD + row] = v.w;
    }

    int tx = t & 63, ty = t >> 6;        // tx: 4 l, ty: 8-row group (uniform/warp)
    int l0 = l0b + tx * 4;
    u64 E[4][4], O[4][4];                // [row-pair][l]
#pragma unroll
    for (int p = 0; p < 4; p++)
#pragma unroll
        for (int u = 0; u < 4; u++) { E[p][u] = 0ull; O[p][u] = 0ull; }

    for (int ch = 0; ch < 4; ch++) {
        __syncthreads();                 // also covers initial saT stores
        // load 16-mode basis chunk: 1024 float4 per table
#pragma unroll
        for (int s = 0; s < 2; s++) {
            int i4 = t + 512 * s;
            int mr = i4 >> 6, j4 = i4 & 63;
            *(float4*)&sbc[mr * 256 + j4 * 4] =
                *(const float4*)(g_bc + (size_t)(ch * 16 + mr) * KP + l0b + j4 * 4);
            *(float4*)&sbs[mr * 256 + j4 * 4] =
                *(const float4*)(g_bs + (size_t)(ch * 16 + mr) * KP + l0b + j4 * 4);
        }
        __syncthreads();
#pragma unroll
        for (int mm = 0; mm < 16; mm++) {
            int m = ch * 16 + mm;
            // a: row-pairs (uniform per warp): Re at saT[m], Im at saT[64+m]
            const float* pre = &saT[m * SAT_PAD + ty * 8];
            const float* pim = &saT[(64 + m) * SAT_PAD + ty * 8];
            u64 aRe[4], aIm[4];
#pragma unroll
            for (int p = 0; p < 4; p++) {
                aRe[p] = *(const u64*)(pre + 2 * p);
                aIm[p] = *(const u64*)(pim + 2 * p);
            }
            float4 c4 = *(const float4*)&sbc[mm * 256 + tx * 4];
            float4 s4 = *(const float4*)&sbs[mm * 256 + tx * 4];
            float cv[4] = {c4.x, c4.y, c4.z, c4.w};
            float sv[4] = {s4.x, s4.y, s4.z, s4.w};
#pragma unroll
            for (int u = 0; u < 4; u++) {
                u64 cd = dup(cv[u]);
                u64 sd = dup(sv[u]);
#pragma unroll
                for (int p = 0; p < 4; p++) {
                    fma2(E[p][u], aRe[p], cd);
                    fma2(O[p][u], aIm[p], sd);
                }
            }
        }
    }

    // write out: lanes are rows (2p, 2p+1)
#pragma unroll
    for (int p = 0; p < 4; p++) {
        int r0 = rowBase + ty * 8 + 2 * p;
        int r1 = r0 + 1;
        float e0[4], e1[4], o0[4], o1[4];
#pragma unroll
        for (int u = 0; u < 4; u++) {
            float2 e2 = unpk(E[p][u]);
            float2 o2 = unpk(O[p][u]);
            e0[u] = e2.x; e1[u] = e2.y;
            o0[u] = o2.x; o1[u] = o2.y;
        }
        *(float4*)(out + (size_t)r0 * Lx + l0) =
            make_float4(e0[0] + o0[0], e0[1] + o0[1], e0[2] + o0[2], e0[3] + o0[3]);
        *(float4*)(out + (size_t)r1 * Lx + l0) =
            make_float4(e1[0] + o1[0], e1[1] + o1[1], e1[2] + o1[2], e1[3] + o1[3]);
#pragma unroll
        for (int u = 0; u < 4; u++) {
            int l = l0 + u;
            if (l > 0) {
                out[(size_t)r0 * Lx + (Lx - l)] = e0[u] - o0[u];
                out[(size_t)r1 * Lx + (Lx - l)] = e1[u] - o1[u];
            }
        }
    }
}

// ---------------------------------------------------------------------------
// K5: l = 2048 edge. bc[m][2048] = (-1)^m, bs term = 0.
// ---------------------------------------------------------------------------
__global__ void k_edge(float* __restrict__ out) {
    int row = blockIdx.x * blockDim.x + threadIdx.x;  // 0..2047
    const float* r = g_res + (size_t)row * 128;
    float s = 0.f;
#pragma unroll
    for (int m = 0; m < 64; m += 2) { s += r[m]; s -= r[m + 1]; }
    out[(size_t)row * Lx + 2048] = s;
}

// ---------------------------------------------------------------------------
extern "C" void kernel_launch(void* const* d_in, const int* in_sizes, int n_in,
                              void* d_out, int out_size) {
    const float* q  = (const float*)d_in[0];
    // d_in[1]=k, d_in[2]=v unused by reference
    const float* wr = (const float*)d_in[3];
    const float* wi = (const float*)d_in[4];
    float* out = (float*)d_out;

    cudaFuncSetAttribute(k_inv, cudaFuncAttributeMaxDynamicSharedMemorySize, SMEM_INV);

    k_basis<<<(Mx * KP + 255) / 256, 256>>>();
    k_basisT<<<(Mx * KP + 255) / 256, 256>>>();
    k_zeroX<<<(8 * Mx * Cx / 4) / 256, 256>>>();
    {
        dim3 g(2, NSPLIT, Bx);   // 2 c-tiles x 18 splits x 4 b = 144 blocks
        k_fwd<<<g, 512>>>(q);    // <- 4th launch: profiled by ncu
    }
    k_reduce<<<256, 256>>>();
    {
        dim3 g(16, 8, 4);
        k_mix<<<g, 256>>>(wr, wi);
    }
    {
        dim3 g(8, 32);           // 8 l-tiles x 32 row-blocks = 256 blocks
        k_inv<<<g, 512, SMEM_INV>>>(out);
    }
    k_edge<<<8, 256>>>(out);
}

// round 5
// speedup vs baseline: 1.5215x; 1.1271x over previous
#include <cuda_runtime.h>
#include <math.h>

// Problem constants
#define Bx 4
#define Lx 4096
#define Hx 8
#define Ex 64
#define Mx 64
#define Cx 512            // H*E
#define KP 2304           // padded folded K (>= 2049), = 18*128
#define NSPLIT 18
#define KCHUNK 128

typedef unsigned long long u64;

// Static device scratch (no allocations allowed)
__device__ float g_bc[Mx * KP];                 // cos(2*pi*m*l/L), [m][l], pads 0
__device__ float g_bs[Mx * KP];                 // -sin(...),       [m][l], pads 0
__device__ float g_bcT[KP * Mx];                // transposed [l][m]
__device__ float g_bsT[KP * Mx];
__device__ float g_part[8 * NSPLIT * Mx * Cx];  // split-K partials
__device__ float g_X[8 * Mx * Cx];              // X[bp][m][c], bp = b*2 + (0:Re,1:Im)
__device__ float g_res[Bx * Cx * 2 * Mx];       // res[b][c][0..63 ReS | 64..127 ImS]

// packed f32x2 helpers
__device__ __forceinline__ void fma2(u64& d, u64 a, u64 b) {
    asm("fma.rn.f32x2 %0, %1, %2, %0;" : "+l"(d) : "l"(a), "l"(b));
}
__device__ __forceinline__ float2 unpk(u64 v) {
    float2 r;
    asm("mov.b64 {%0, %1}, %2;" : "=f"(r.x), "=f"(r.y) : "l"(v));
    return r;
}
__device__ __forceinline__ u64 dup(float v) {
    u64 r;
    asm("mov.b64 %0, {%1, %1};" : "=l"(r) : "f"(v));
    return r;
}

// ---------------------------------------------------------------------------
// K0a: build basis tables [m][l].
// ---------------------------------------------------------------------------
__global__ void k_basis() {
    int id = blockIdx.x * blockDim.x + threadIdx.x;
    if (id >= Mx * KP) return;
    int m = id / KP, l = id - m * KP;
    float c = 0.f, s = 0.f;
    if (l <= 2048) {
        int r = (m * l) & (Lx - 1);
        sincospif((float)r / 2048.0f, &s, &c);
    }
    g_bc[m * KP + l] = c;
    g_bs[m * KP + l] = -s;
}

// ---------------------------------------------------------------------------
// K0b: transpose basis -> [l][m]
// ---------------------------------------------------------------------------
__global__ void k_basisT() {
    int id = blockIdx.x * blockDim.x + threadIdx.x;
    if (id >= Mx * KP) return;
    int l = id / Mx, m = id - l * Mx;
    g_bcT[(size_t)l * Mx + m] = g_bc[(size_t)m * KP + l];
    g_bsT[(size_t)l * Mx + m] = g_bs[(size_t)m * KP + l];
}

// ---------------------------------------------------------------------------
// K0c: zero g_X (keeps k_fwd at launch position 4 for ncu)
// ---------------------------------------------------------------------------
__global__ void k_zeroX() {
    int o = blockIdx.x * blockDim.x + threadIdx.x;
    ((float4*)g_X)[o] = make_float4(0.f, 0.f, 0.f, 0.f);
}

// ---------------------------------------------------------------------------
// K1: forward GEMM, split-K, fold fused, Re+Im fused, packed FFMA2,
// register double-buffered (LDG prefetch overlaps compute).
//   Re[m][c] = sum_l bc[m][l] * (q[l]+q[L-l])[c]
//   Im[m][c] = sum_l bs[m][l] * (q[l]-q[L-l])[c]
// Block: 64 m x 128 c, 256 threads, per thread 8m x 4c, 2 blocks/SM.
// ---------------------------------------------------------------------------
__global__ void __launch_bounds__(256, 2) k_fwd(const float* __restrict__ q) {
    __shared__ float2 Bsum[8][64];   // [kk][c/2]
    __shared__ float2 Bdif[8][64];
    __shared__ float  Acs[8][64];    // [kk][m]
    __shared__ float  Ass[8][64];

    const int t = threadIdx.x;
    const int ct = blockIdx.x;      // 0..3  (c-tile of 128)
    const int split = blockIdx.y;   // 0..17
    const int b = blockIdx.z;       // 0..3
    const int c0 = ct * 128;
    const int k0 = split * KCHUNK;
    const int tx = t & 31, ty = t >> 5;    // tx: 4c, ty: 8m (uniform/warp)
    const int bkk = t >> 5, bcg = t & 31;  // B loader: 8kk x 32 float4
    const int akk = t >> 4, amg = t & 15;  // A loader: 8kk x 16 float4 (t<128)
    const bool aload = (t < 128);
    const float* qb = q + (size_t)b * Lx * Cx;

    u64 accRe[8][2], accIm[8][2];
#pragma unroll
    for (int r = 0; r < 8; r++) {
        accRe[r][0] = accRe[r][1] = 0ull;
        accIm[r][0] = accIm[r][1] = 0ull;
    }

    float4 pa, pmm, pac, pas;
    // prologue: prefetch chunk k0
    {
        int l = k0 + bkk;
        pa = make_float4(0.f, 0.f, 0.f, 0.f); pmm = pa;
        if (l <= 2048) {
            pa = *(const float4*)(qb + (size_t)l * Cx + c0 + bcg * 4);
            if (l == 0 || l == 2048) {
                pa.x *= 0.5f; pa.y *= 0.5f; pa.z *= 0.5f; pa.w *= 0.5f;
                pmm = pa;     // so vs = pa_orig, vd = 0
            } else {
                pmm = *(const float4*)(qb + (size_t)(Lx - l) * Cx + c0 + bcg * 4);
            }
        }
        if (aload) {
            pac = *(const float4*)(g_bcT + (size_t)(k0 + akk) * Mx + amg * 4);
            pas = *(const float4*)(g_bsT + (size_t)(k0 + akk) * Mx + amg * 4);
        }
    }

    for (int kc = k0; kc < k0 + KCHUNK; kc += 8) {
        // store prefetched chunk (fold fused)
        {
            float4 vs = make_float4(pa.x + pmm.x, pa.y + pmm.y, pa.z + pmm.z, pa.w + pmm.w);
            float4 vd = make_float4(pa.x - pmm.x, pa.y - pmm.y, pa.z - pmm.z, pa.w - pmm.w);
            *(float4*)&Bsum[bkk][bcg * 2] = vs;
            *(float4*)&Bdif[bkk][bcg * 2] = vd;
            if (aload) {
                *(float4*)&Acs[akk][amg * 4] = pac;
                *(float4*)&Ass[akk][amg * 4] = pas;
            }
        }
        __syncthreads();
        // prefetch next chunk (LDG latency hidden by compute below)
        if (kc + 8 < k0 + KCHUNK) {
            int l = kc + 8 + bkk;
            pa = make_float4(0.f, 0.f, 0.f, 0.f); pmm = pa;
            if (l <= 2048) {
                pa = *(const float4*)(qb + (size_t)l * Cx + c0 + bcg * 4);
                if (l == 0 || l == 2048) {
                    pa.x *= 0.5f; pa.y *= 0.5f; pa.z *= 0.5f; pa.w *= 0.5f;
                    pmm = pa;
                } else {
                    pmm = *(const float4*)(qb + (size_t)(Lx - l) * Cx + c0 + bcg * 4);
                }
            }
            if (aload) {
                pac = *(const float4*)(g_bcT + (size_t)(kc + 8 + akk) * Mx + amg * 4);
                pas = *(const float4*)(g_bsT + (size_t)(kc + 8 + akk) * Mx + amg * 4);
            }
        }
        // compute 8 kk
#pragma unroll
        for (int kk = 0; kk < 8; kk++) {
            float4 bq = *(const float4*)&Bsum[kk][tx * 2];   // b0|b1
            float4 dq = *(const float4*)&Bdif[kk][tx * 2];   // d0|d1
            u64 b0 = *(u64*)&bq.x, b1 = *(u64*)&bq.z;
            u64 d0 = *(u64*)&dq.x, d1 = *(u64*)&dq.z;
            float4 ac0 = *(const float4*)&Acs[kk][ty * 8];   // uniform
            float4 ac1 = *(const float4*)&Acs[kk][ty * 8 + 4];
            float4 as0 = *(const float4*)&Ass[kk][ty * 8];
            float4 as1 = *(const float4*)&Ass[kk][ty * 8 + 4];
            float acv[8] = {ac0.x, ac0.y, ac0.z, ac0.w, ac1.x, ac1.y, ac1.z, ac1.w};
            float asv[8] = {as0.x, as0.y, as0.z, as0.w, as1.x, as1.y, as1.z, as1.w};
#pragma unroll
            for (int r = 0; r < 8; r++) {
                u64 a2 = dup(acv[r]);
                u64 s2 = dup(asv[r]);
                fma2(accRe[r][0], a2, b0);
                fma2(accRe[r][1], a2, b1);
                fma2(accIm[r][0], s2, d0);
                fma2(accIm[r][1], s2, d1);
            }
        }
        __syncthreads();
    }

    float* oRe = g_part + ((size_t)(b * 2 + 0) * NSPLIT + split) * (Mx * Cx);
    float* oIm = g_part + ((size_t)(b * 2 + 1) * NSPLIT + split) * (Mx * Cx);
#pragma unroll
    for (int r = 0; r < 8; r++) {
        int m = ty * 8 + r;
        float2 lo = unpk(accRe[r][0]), hi = unpk(accRe[r][1]);
        *(float4*)(oRe + (size_t)m * Cx + c0 + tx * 4) =
            make_float4(lo.x, lo.y, hi.x, hi.y);
        float2 lo2 = unpk(accIm[r][0]), hi2 = unpk(accIm[r][1]);
        *(float4*)(oIm + (size_t)m * Cx + c0 + tx * 4) =
            make_float4(lo2.x, lo2.y, hi2.x, hi2.y);
    }
}

// ---------------------------------------------------------------------------
// K2: reduce split-K partials -> g_X (float4)
// ---------------------------------------------------------------------------
__global__ void k_reduce() {
    int o4 = blockIdx.x * blockDim.x + threadIdx.x;  // 0..65535 (float4 units)
    int bp = o4 >> 13;           // 8192 float4 per bp
    int inner = o4 & 8191;
    const float4* p = (const float4*)g_part + (size_t)bp * NSPLIT * 8192 + inner;
    float4 s = make_float4(0.f, 0.f, 0.f, 0.f);
#pragma unroll
    for (int sp = 0; sp < NSPLIT; sp++) {
        float4 v = p[(size_t)sp * 8192];
        s.x += v.x; s.y += v.y; s.z += v.z; s.w += v.w;
    }
    ((float4*)g_X)[o4] = s;
}

// ---------------------------------------------------------------------------
// K3: head mixing + irfft scaling. Block = (e-quad, o, b); 256 threads (m,eq).
// ---------------------------------------------------------------------------
__global__ void k_mix(const float* __restrict__ wr, const float* __restrict__ wi) {
    __shared__ float sX[2][8][4][64];   // [re/im][i][eq][m]
    int t = threadIdx.x;
    int eq4 = blockIdx.x;   // 0..15 -> e0 = eq4*4
    int o = blockIdx.y;     // 0..7
    int b = blockIdx.z;     // 0..3
    int e0 = eq4 * 4;

#pragma unroll
    for (int s = 0; s < 4; s++) {
        int idx = t + 256 * s;
        int tab = idx >> 9;
        int rem = idx & 511;
        int m = rem >> 3, i = rem & 7;
        float4 v = *(const float4*)(g_X + ((size_t)(b * 2 + tab) * Mx + m) * Cx + i * 64 + e0);
        sX[tab][i][0][m] = v.x;
        sX[tab][i][1][m] = v.y;
        sX[tab][i][2][m] = v.z;
        sX[tab][i][3][m] = v.w;
    }
    __syncthreads();

    int m = t & 63, eqi = t >> 6;
    int e = e0 + eqi;
    float re = 0.f, im = 0.f;
#pragma unroll
    for (int i = 0; i < Hx; i++) {
        float xr = sX[0][i][eqi][m];
        float xi = sX[1][i][eqi][m];
        size_t wIdx = (((size_t)i * Hx + o) * Ex + e) * Mx + m;
        float wre = wr[wIdx], wim = wi[wIdx];
        re += xr * wre - xi * wim;
        im += xr * wim + xi * wre;
    }
    float scR = (m == 0) ? (1.0f / Lx) : (2.0f / Lx);
    float* r = g_res + ((size_t)(b * Cx) + o * Ex + e) * 128;
    r[m] = re * scR;
    r[64 + m] = (m == 0) ? 0.f : im * (2.0f / Lx);
}

// ---------------------------------------------------------------------------
// K4: inverse synthesis, row-pairs packed in f32x2 lanes, basis double-buffer.
//   E[l] = sum_m ReS*bc[m][l];  O[l] = sum_m ImS*bs[m][l]
//   out[l] = E+O (l<2048); out[L-l] = E-O (l=1..2047)
// Block: 64 rows x 128 l, 256 threads, per thread 8 rows x 4 l, 2 blocks/SM.
// Dynamic smem: saT[128][68] (transposed res) + sbc/sbs[16][128].
// ---------------------------------------------------------------------------
#define SAT_PAD 68
#define SMEM_INV (128 * SAT_PAD * 4 + 2 * 16 * 128 * 4)

__global__ void __launch_bounds__(256, 2) k_inv(float* __restrict__ out) {
    extern __shared__ float sm[];
    float* saT = sm;                         // [j=0..127][row 0..63], stride 68
    float* sbc = sm + 128 * SAT_PAD;         // [16][128]
    float* sbs = sbc + 16 * 128;

    const int t = threadIdx.x;
    const int ltile = blockIdx.x;              // 0..15 (128 l each)
    const int rowBase = blockIdx.y * 64;       // 0..31
    const int l0b = ltile * 128;

    // load g_res into transposed saT (conflict-free column stores)
#pragma unroll
    for (int s = 0; s < 8; s++) {
        int i4 = t + 256 * s;
        int row = i4 & 63, j4 = i4 >> 6;     // j4 0..31
        float4 v = *(const float4*)(g_res + (size_t)(rowBase + row) * 128 + j4 * 4);
        saT[(j4 * 4 + 0) * SAT_PAD + row] = v.x;
        saT[(j4 * 4 + 1) * SAT_PAD + row] = v.y;
        saT[(j4 * 4 + 2) * SAT_PAD + row] = v.z;
        saT[(j4 * 4 + 3) * SAT_PAD + row] = v.w;
    }

    const int tx = t & 31, ty = t >> 5;      // tx: 4 l, ty: 8-row group (uniform/warp)
    const int l0 = l0b + tx * 4;
    // basis loader: 512 float4 per table per chunk; 256 threads x 2
    const int mr0 = t >> 5, j40 = t & 31;            // s=0: mr 0..7
    const int mr1 = (t + 256) >> 5, j41 = t & 31;    // s=1: mr 8..15

    u64 E[4][4], O[4][4];                // [row-pair][l]
#pragma unroll
    for (int p = 0; p < 4; p++)
#pragma unroll
        for (int u = 0; u < 4; u++) { E[p][u] = 0ull; O[p][u] = 0ull; }

    // prefetch basis chunk 0
    float4 rbc0, rbc1, rbs0, rbs1;
    rbc0 = *(const float4*)(g_bc + (size_t)(mr0) * KP + l0b + j40 * 4);
    rbc1 = *(const float4*)(g_bc + (size_t)(mr1) * KP + l0b + j41 * 4);
    rbs0 = *(const float4*)(g_bs + (size_t)(mr0) * KP + l0b + j40 * 4);
    rbs1 = *(const float4*)(g_bs + (size_t)(mr1) * KP + l0b + j41 * 4);

    for (int ch = 0; ch < 4; ch++) {
        __syncthreads();       // prev compute done (covers saT stores at ch=0)
        *(float4*)&sbc[mr0 * 128 + j40 * 4] = rbc0;
        *(float4*)&sbc[mr1 * 128 + j41 * 4] = rbc1;
        *(float4*)&sbs[mr0 * 128 + j40 * 4] = rbs0;
        *(float4*)&sbs[mr1 * 128 + j41 * 4] = rbs1;
        __syncthreads();
        if (ch < 3) {
            int mb = (ch + 1) * 16;
            rbc0 = *(const float4*)(g_bc + (size_t)(mb + mr0) * KP + l0b + j40 * 4);
            rbc1 = *(const float4*)(g_bc + (size_t)(mb + mr1) * KP + l0b + j41 * 4);
            rbs0 = *(const float4*)(g_bs + (size_t)(mb + mr0) * KP + l0b + j40 * 4);
            rbs1 = *(const float4*)(g_bs + (size_t)(mb + mr1) * KP + l0b + j41 * 4);
        }
#pragma unroll
        for (int mm = 0; mm < 16; mm++) {
            int m = ch * 16 + mm;
            const float* pre = &saT[(size_t)m * SAT_PAD + ty * 8];
            const float* pim = &saT[(size_t)(64 + m) * SAT_PAD + ty * 8];
            float4 q0 = *(const float4*)pre;         // rows 0..3 of group (uniform)
            float4 q1 = *(const float4*)(pre + 4);   // rows 4..7
            float4 w0 = *(const float4*)pim;
            float4 w1 = *(const float4*)(pim + 4);
            u64 aRe[4] = {*(u64*)&q0.x, *(u64*)&q0.z, *(u64*)&q1.x, *(u64*)&q1.z};
            u64 aIm[4] = {*(u64*)&w0.x, *(u64*)&w0.z, *(u64*)&w1.x, *(u64*)&w1.z};
            float4 c4 = *(const float4*)&sbc[mm * 128 + tx * 4];
            float4 s4 = *(const float4*)&sbs[mm * 128 + tx * 4];
            float cv[4] = {c4.x, c4.y, c4.z, c4.w};
            float sv[4] = {s4.x, s4.y, s4.z, s4.w};
#pragma unroll
            for (int u = 0; u < 4; u++) {
                u64 cd = dup(cv[u]);
                u64 sd = dup(sv[u]);
#pragma unroll
                for (int p = 0; p < 4; p++) {
                    fma2(E[p][u], aRe[p], cd);
                    fma2(O[p][u], aIm[p], sd);
                }
            }
        }
    }

    // write out: f32x2 lanes are row-pairs (2p, 2p+1)
#pragma unroll
    for (int p = 0; p < 4; p++) {
        int r0 = rowBase + ty * 8 + 2 * p;
        int r1 = r0 + 1;
        float e0[4], e1[4], o0[4], o1[4];
#pragma unroll
        for (int u = 0; u < 4; u++) {
            float2 e2 = unpk(E[p][u]);
            float2 o2 = unpk(O[p][u]);
            e0[u] = e2.x; e1[u] = e2.y;
            o0[u] = o2.x; o1[u] = o2.y;
        }
        *(float4*)(out + (size_t)r0 * Lx + l0) =
            make_float4(e0[0] + o0[0], e0[1] + o0[1], e0[2] + o0[2], e0[3] + o0[3]);
        *(float4*)(out + (size_t)r1 * Lx + l0) =
            make_float4(e1[0] + o1[0], e1[1] + o1[1], e1[2] + o1[2], e1[3] + o1[3]);
#pragma unroll
        for (int u = 0; u < 4; u++) {
            int l = l0 + u;
            if (l > 0) {
                out[(size_t)r0 * Lx + (Lx - l)] = e0[u] - o0[u];
                out[(size_t)r1 * Lx + (Lx - l)] = e1[u] - o1[u];
            }
        }
    }
}

// ---------------------------------------------------------------------------
// K5: l = 2048 edge. bc[m][2048] = (-1)^m, bs term = 0.
// ---------------------------------------------------------------------------
__global__ void k_edge(float* __restrict__ out) {
    int row = blockIdx.x * blockDim.x + threadIdx.x;  // 0..2047
    const float* r = g_res + (size_t)row * 128;
    float s = 0.f;
#pragma unroll
    for (int m = 0; m < 64; m += 2) { s += r[m]; s -= r[m + 1]; }
    out[(size_t)row * Lx + 2048] = s;
}

// ---------------------------------------------------------------------------
extern "C" void kernel_launch(void* const* d_in, const int* in_sizes, int n_in,
                              void* d_out, int out_size) {
    const float* q  = (const float*)d_in[0];
    // d_in[1]=k, d_in[2]=v unused by reference
    const float* wr = (const float*)d_in[3];
    const float* wi = (const float*)d_in[4];
    float* out = (float*)d_out;

    cudaFuncSetAttribute(k_inv, cudaFuncAttributeMaxDynamicSharedMemorySize, SMEM_INV);

    k_basis<<<(Mx * KP + 255) / 256, 256>>>();
    k_basisT<<<(Mx * KP + 255) / 256, 256>>>();
    k_zeroX<<<(8 * Mx * Cx / 4) / 256, 256>>>();
    {
        dim3 g(4, NSPLIT, Bx);   // 4 c-tiles x 18 splits x 4 b = 288 blocks
        k_fwd<<<g, 256>>>(q);    // <- 4th launch: profiled by ncu
    }
    k_reduce<<<256, 256>>>();
    {
        dim3 g(16, 8, 4);
        k_mix<<<g, 256>>>(wr, wi);
    }
    {
        dim3 g(16, 32);          // 16 l-tiles x 32 row-blocks = 512 blocks
        k_inv<<<g, 256, SMEM_INV>>>(out);
    }
    k_edge<<<8, 256>>>(out);
}